// round 7
// baseline (speedup 1.0000x reference)
#include <cuda_runtime.h>
#include <float.h>

// WOS: weighted order statistic, O(D^2/2) symmetric rank-by-counting.
// Pair (i<j) compared once via FSET (m = 1.0/0.0, pred-as-data, lat 4) and
// charged with two FFMAs: acc_j += m*w_i ; acc_i -= m*w_j, where acc_i is
// initialized to the suffix sum sum_{k>=i} w_k (folds the (1-m)*w_j branch).
// Removes all predicate-guard latency (13 cyc) from the hot loop.

#define NCH   16
#define DTOT  54
#define DHALF 27
#define TOL   1e-6f
#define JT    18          // j-tile size (3 tiles)
#define PX    8           // pixels per block

__device__ __forceinline__ float fset_ge(float a, float b) {
    float m;
    asm("set.ge.f32.f32 %0, %1, %2;" : "=f"(m) : "f"(a), "f"(b));
    return m;   // 1.0f if a>=b else 0.0f
}

__global__ __launch_bounds__(128, 3)
void wos_kernel(const float* __restrict__ x,
                const float* __restrict__ mask,
                const float* __restrict__ weight,
                const float* __restrict__ bias,
                float* __restrict__ out)
{
    __shared__ float msk[NCH * DTOT];       // mask per nc
    __shared__ float wgs[NCH * DTOT];       // gated weights: w>tol ? w : 0
    __shared__ float ptile[3][3][PX + 2];   // [c][kh][col] halo for PX pixels

    const int tid = threadIdx.x + threadIdx.y * 16;   // x = nc(16), y = pixel(PX)

    for (int e = tid; e < NCH * DTOT; e += 128) {
        msk[e] = mask[e];
        float w = weight[e];
        wgs[e] = (w > TOL) ? w : 0.0f;
    }

    const int n0  = blockIdx.x * PX;        // PX consecutive pixels, same (b,h)
    const int b   = n0 >> 12;
    const int rem = n0 & 4095;
    const int h   = rem >> 6;
    const int w0  = rem & 63;

    for (int e = tid; e < 3 * 3 * (PX + 2); e += 128) {
        int c   = e / (3 * (PX + 2));
        int r   = (e / (PX + 2)) % 3;
        int col = e % (PX + 2);
        int gr  = h - 1 + r;
        int gc  = w0 - 1 + col;
        float v = 0.0f;
        if ((unsigned)gr < 64u && (unsigned)gc < 64u)
            v = x[((b * 3 + c) * 64 + gr) * 64 + gc];
        ptile[c][r][col] = v;
    }
    __syncthreads();

    const int nc = threadIdx.x;
    const int py = threadIdx.y;
    const int n  = n0 + py;
    const int mb = nc * DTOT;

    // ---- mx[54] = [p, -p] + mask[nc] ----
    float mx[DTOT];
    #pragma unroll
    for (int c = 0; c < 3; c++)
        #pragma unroll
        for (int r = 0; r < 3; r++)
            #pragma unroll
            for (int kw = 0; kw < 3; kw++) {
                int d = c * 9 + r * 3 + kw;
                float p = ptile[c][r][py + kw];
                mx[d]         = p + msk[mb + d];
                mx[d + DHALF] = msk[mb + d + DHALF] - p;
            }

    // ---- acc_i init = suffix sum of gated weights (includes self) ----
    float acc[DTOT];
    {
        float s = 0.0f;
        #pragma unroll
        for (int d = DTOT - 1; d >= 0; d--) {
            s += wgs[mb + d];
            acc[d] = s;
        }
    }

    // ---- symmetric pair loop, j tiled by JT: FSET + 2 FFMA per pair ----
    #pragma unroll
    for (int t = 0; t < DTOT / JT; t++) {
        const int J0 = t * JT;
        float wj[JT];
        #pragma unroll
        for (int jj = 0; jj < JT; jj++)
            wj[jj] = wgs[mb + J0 + jj];

        #pragma unroll
        for (int i = 0; i < J0 + JT; i++) {
            float mi = mx[i];
            float wi = (i >= J0) ? wj[i - J0] : wgs[mb + i];  // compile-time pick
            float s0 = 0.0f, s1 = 0.0f;                        // split acc_i chain
            #pragma unroll
            for (int jj = 0; jj < JT; jj++) {
                int j = J0 + jj;
                if (j > i) {
                    float m = fset_ge(mi, mx[j]);   // ties: i (<j) sorts first
                    acc[j] = fmaf(m, wi, acc[j]);
                    if (jj & 1) s1 = fmaf(m, wj[jj], s1);
                    else        s0 = fmaf(m, wj[jj], s0);
                }
            }
            if (i < J0 + JT - 1)                    // at least one pair processed
                acc[i] -= (s0 + s1);
        }
    }

    // ---- selection epilogue ----
    const float biasv = bias[nc];
    float selMin = FLT_MAX;
    float fbMax  = -FLT_MAX;
    int found = 0, anynz = 0;

    #pragma unroll
    for (int j = 0; j < DTOT; j++) {
        float wjv = wgs[mb + j];
        if (wjv > 0.0f) {
            anynz = 1;
            float vj = mx[j];
            fbMax = fmaxf(fbMax, vj);
            if (acc[j] <= biasv) {
                found = 1;
                selMin = fminf(selMin, vj);
            }
        }
    }

    float res = found ? selMin : (anynz ? fbMax : 0.0f);
    out[n * NCH + nc] = res;    // flat layout: coalesced per warp
}

extern "C" void kernel_launch(void* const* d_in, const int* in_sizes, int n_in,
                              void* d_out, int out_size) {
    const float* x      = (const float*)d_in[0];
    const float* mask   = (const float*)d_in[1];
    const float* weight = (const float*)d_in[2];
    const float* bias   = (const float*)d_in[3];
    float* out = (float*)d_out;

    // 32768 pixels / 8 per block = 4096 blocks; block = 16 nc x 8 pixels
    wos_kernel<<<4096, dim3(16, PX)>>>(x, mask, weight, bias, out);
}

// round 8
// speedup vs baseline: 1.7931x; 1.7931x over previous
#include <cuda_runtime.h>
#include <float.h>

// WOS: weighted order statistic, O(D^2/2) symmetric rank-by-counting.
// Pair (i<j) compared ONCE: FSETP; @p acc_j += w_i; @!p s += w_j, with the
// loser-side (acc_i) accumulation split across two rotating partials s0/s1
// to break the 17-deep serial RAW chain that capped issue efficiency in R6.

#define NCH   16
#define DTOT  54
#define DHALF 27
#define TOL   1e-6f
#define JT    18          // j-tile size (3 tiles)
#define PX    8           // pixels per block

// i < j by iteration order: ties (>=) put i before j (stable argsort).
// Winner's weight charged to loser: @p (i wins) -> acc_j += wi;
// @!p (j wins) -> s += wj (folded into acc_i by caller).
__device__ __forceinline__ void pair_update(float& accj, float& s,
                                            float mi, float mj,
                                            float wi, float wj) {
    asm volatile("{\n\t"
        ".reg .pred p;\n\t"
        "setp.ge.f32 p, %2, %3;\n\t"
        "@p  add.f32 %0, %0, %4;\n\t"
        "@!p add.f32 %1, %1, %5;\n\t"
        "}" : "+f"(accj), "+f"(s)
            : "f"(mi), "f"(mj), "f"(wi), "f"(wj));
}

__global__ __launch_bounds__(128, 3)
void wos_kernel(const float* __restrict__ x,
                const float* __restrict__ mask,
                const float* __restrict__ weight,
                const float* __restrict__ bias,
                float* __restrict__ out)
{
    __shared__ float msk[NCH * DTOT];       // mask per nc
    __shared__ float wgs[NCH * DTOT];       // gated weights: w>tol ? w : 0
    __shared__ float ptile[3][3][PX + 2];   // [c][kh][col] halo for PX pixels

    const int tid = threadIdx.x + threadIdx.y * 16;   // x = nc(16), y = pixel(PX)

    for (int e = tid; e < NCH * DTOT; e += 128) {
        msk[e] = mask[e];
        float w = weight[e];
        wgs[e] = (w > TOL) ? w : 0.0f;
    }

    const int n0  = blockIdx.x * PX;        // PX consecutive pixels, same (b,h)
    const int b   = n0 >> 12;
    const int rem = n0 & 4095;
    const int h   = rem >> 6;
    const int w0  = rem & 63;

    for (int e = tid; e < 3 * 3 * (PX + 2); e += 128) {
        int c   = e / (3 * (PX + 2));
        int r   = (e / (PX + 2)) % 3;
        int col = e % (PX + 2);
        int gr  = h - 1 + r;
        int gc  = w0 - 1 + col;
        float v = 0.0f;
        if ((unsigned)gr < 64u && (unsigned)gc < 64u)
            v = x[((b * 3 + c) * 64 + gr) * 64 + gc];
        ptile[c][r][col] = v;
    }
    __syncthreads();

    const int nc = threadIdx.x;
    const int py = threadIdx.y;
    const int n  = n0 + py;
    const int mb = nc * DTOT;

    // ---- mx[54] = [p, -p] + mask[nc] ----
    float mx[DTOT];
    #pragma unroll
    for (int c = 0; c < 3; c++)
        #pragma unroll
        for (int r = 0; r < 3; r++)
            #pragma unroll
            for (int kw = 0; kw < 3; kw++) {
                int d = c * 9 + r * 3 + kw;
                float p = ptile[c][r][py + kw];
                mx[d]         = p + msk[mb + d];
                mx[d + DHALF] = msk[mb + d + DHALF] - p;
            }

    // ---- inclusive accumulators start at own gated weight ----
    float acc[DTOT];
    #pragma unroll
    for (int d = 0; d < DTOT; d++)
        acc[d] = wgs[mb + d];

    // ---- symmetric pair loop, j tiled by JT ----
    #pragma unroll
    for (int t = 0; t < DTOT / JT; t++) {
        const int J0 = t * JT;
        float wj[JT];
        #pragma unroll
        for (int jj = 0; jj < JT; jj++)
            wj[jj] = wgs[mb + J0 + jj];

        #pragma unroll
        for (int i = 0; i < J0 + JT; i++) {
            float mi = mx[i];
            float wi = (i >= J0) ? wj[i - J0] : wgs[mb + i];  // compile-time pick
            float s0 = 0.0f, s1 = 0.0f;     // split loser-side chains
            #pragma unroll
            for (int jj = 0; jj < JT; jj++) {
                int j = J0 + jj;
                if (j > i)
                    pair_update(acc[j], (jj & 1) ? s1 : s0,
                                mi, mx[j], wi, wj[jj]);
            }
            if (i < J0 + JT - 1)            // at least one pair processed
                acc[i] += s0 + s1;
        }
    }

    // ---- selection epilogue ----
    const float biasv = bias[nc];
    float selMin = FLT_MAX;
    float fbMax  = -FLT_MAX;
    int found = 0, anynz = 0;

    #pragma unroll
    for (int j = 0; j < DTOT; j++) {
        float wjv = wgs[mb + j];
        if (wjv > 0.0f) {
            anynz = 1;
            float vj = mx[j];
            fbMax = fmaxf(fbMax, vj);
            if (acc[j] <= biasv) {
                found = 1;
                selMin = fminf(selMin, vj);
            }
        }
    }

    float res = found ? selMin : (anynz ? fbMax : 0.0f);
    out[n * NCH + nc] = res;    // flat layout: coalesced per warp
}

extern "C" void kernel_launch(void* const* d_in, const int* in_sizes, int n_in,
                              void* d_out, int out_size) {
    const float* x      = (const float*)d_in[0];
    const float* mask   = (const float*)d_in[1];
    const float* weight = (const float*)d_in[2];
    const float* bias   = (const float*)d_in[3];
    float* out = (float*)d_out;

    // 32768 pixels / 8 per block = 4096 blocks; block = 16 nc x 8 pixels
    wos_kernel<<<4096, dim3(16, PX)>>>(x, mask, weight, bias, out);
}